// round 3
// baseline (speedup 1.0000x reference)
#include <cuda_runtime.h>
#include <math_constants.h>

// Problem constants
#define B_   4
#define C_   256
#define C8_  32
#define N_   4096

// Scratch (static device globals — no runtime allocation)
// g_Q: FA "keys"    = Wq@x + bq, layout [b][j][n]
// g_K: FA "queries" = Wk@x + bk, layout [b][j][m]
// g_V: values       = Wv@x + bv, layout [b][c][n]
__device__ float g_Q[B_ * C8_ * N_];
__device__ float g_K[B_ * C8_ * N_];
__device__ float g_V[B_ * C_ * N_];

// ---------------------------------------------------------------------------
// Projection: out[b][j][n] = sum_c W[j][c] * x[b][c][n] + bias[j],  j in [0,32)
// Block tile: 32 j x 128 n. 256 threads, each computes 4j x 4n.
// which = 0 -> g_Q, which = 1 -> g_K
// ---------------------------------------------------------------------------
__global__ __launch_bounds__(256) void proj32_kernel(
    const float* __restrict__ x, const float* __restrict__ W,
    const float* __restrict__ bias, int which)
{
    float* __restrict__ out = which ? g_K : g_Q;
    const int b  = blockIdx.y;
    const int n0 = blockIdx.x * 128;
    __shared__ float Xs[32][132];   // [c][n], pad to 132 for bank spread
    __shared__ float Ws[32][33];    // [j][c]
    const int tid = threadIdx.x;
    const int nl  = tid & 31;       // n lane
    const int jg  = tid >> 5;       // j group (0..7)

    float acc[4][4];
#pragma unroll
    for (int i = 0; i < 4; i++)
#pragma unroll
        for (int k = 0; k < 4; k++) acc[i][k] = 0.f;

    for (int c0 = 0; c0 < C_; c0 += 32) {
        for (int idx = tid; idx < 32 * 128; idx += 256) {
            int cc = idx >> 7, nn = idx & 127;
            Xs[cc][nn] = x[(((b << 8) + c0 + cc) << 12) + n0 + nn];
        }
        for (int idx = tid; idx < 1024; idx += 256) {
            int jj = idx >> 5, cc = idx & 31;
            Ws[jj][cc] = W[(jj << 8) + c0 + cc];
        }
        __syncthreads();
#pragma unroll
        for (int cc = 0; cc < 32; cc++) {
            float wv[4], xv[4];
#pragma unroll
            for (int ji = 0; ji < 4; ji++) wv[ji] = Ws[jg + 8 * ji][cc];
#pragma unroll
            for (int ni = 0; ni < 4; ni++) xv[ni] = Xs[cc][nl + 32 * ni];
#pragma unroll
            for (int ji = 0; ji < 4; ji++)
#pragma unroll
                for (int ni = 0; ni < 4; ni++) acc[ji][ni] += wv[ji] * xv[ni];
        }
        __syncthreads();
    }
#pragma unroll
    for (int ji = 0; ji < 4; ji++) {
        int j = jg + 8 * ji;
        float bj = bias[j];
#pragma unroll
        for (int ni = 0; ni < 4; ni++) {
            out[(((b << 5) + j) << 12) + n0 + nl + 32 * ni] = acc[ji][ni] + bj;
        }
    }
}

// ---------------------------------------------------------------------------
// V projection: out[b][c][n] = sum_p Wv[c][p] * x[b][p][n] + bv[c]
// Block tile: 64 c x 64 n. 256 threads (16x16), each computes 4c x 4n.
// ---------------------------------------------------------------------------
__global__ __launch_bounds__(256) void projv_kernel(
    const float* __restrict__ x, const float* __restrict__ W,
    const float* __restrict__ bias)
{
    const int b  = blockIdx.z;
    const int c0 = blockIdx.y * 64;
    const int n0 = blockIdx.x * 64;
    __shared__ float Xs[64][68];    // [p][n]
    __shared__ float WsT[64][68];   // [p][c]
    const int tid = threadIdx.x;
    const int tx = tid & 15;        // n quad: n = n0 + tx*4 + {0..3}
    const int ty = tid >> 4;        // c quad: c = c0 + ty*4 + {0..3}

    float acc[4][4];
#pragma unroll
    for (int i = 0; i < 4; i++)
#pragma unroll
        for (int k = 0; k < 4; k++) acc[i][k] = 0.f;

    for (int p0 = 0; p0 < C_; p0 += 64) {
        for (int idx = tid; idx < 4096; idx += 256) {
            int pp = idx >> 6, nn = idx & 63;
            Xs[pp][nn] = x[(((b << 8) + p0 + pp) << 12) + n0 + nn];
        }
        for (int idx = tid; idx < 4096; idx += 256) {
            int cc = idx >> 6, pp = idx & 63;
            WsT[pp][cc] = W[((c0 + cc) << 8) + p0 + pp];
        }
        __syncthreads();
#pragma unroll
        for (int pp = 0; pp < 64; pp++) {
            const float4 a  = *(const float4*)&WsT[pp][ty * 4];
            const float4 xb = *(const float4*)&Xs[pp][tx * 4];
            acc[0][0] += a.x * xb.x; acc[0][1] += a.x * xb.y;
            acc[0][2] += a.x * xb.z; acc[0][3] += a.x * xb.w;
            acc[1][0] += a.y * xb.x; acc[1][1] += a.y * xb.y;
            acc[1][2] += a.y * xb.z; acc[1][3] += a.y * xb.w;
            acc[2][0] += a.z * xb.x; acc[2][1] += a.z * xb.y;
            acc[2][2] += a.z * xb.z; acc[2][3] += a.z * xb.w;
            acc[3][0] += a.w * xb.x; acc[3][1] += a.w * xb.y;
            acc[3][2] += a.w * xb.z; acc[3][3] += a.w * xb.w;
        }
        __syncthreads();
    }
#pragma unroll
    for (int i = 0; i < 4; i++) {
        int c = c0 + ty * 4 + i;
        float bc = bias[c];
        float4 r = make_float4(acc[i][0] + bc, acc[i][1] + bc,
                               acc[i][2] + bc, acc[i][3] + bc);
        *(float4*)&g_V[(((size_t)(b << 8) + c) << 12) + n0 + tx * 4] = r;
    }
}

// ---------------------------------------------------------------------------
// Flash attention (softmax over n, per output column m):
//   S[n,m] = sum_j g_Q[b][j][n] * g_K[b][j][m]
//   A = softmax_n(S);  out[c][m] = gamma * sum_n g_V[c][n] A[n,m] / l + x[c][m]
// Block: 32 m positions, 256 threads. Thread (ml = tid/8, g = tid%8) owns
// query m0+ml and channels c = g + 8k, k in [0,32).
// ---------------------------------------------------------------------------
__global__ __launch_bounds__(256) void attn_kernel(
    const float* __restrict__ xin, const float* __restrict__ gamma,
    float* __restrict__ out)
{
    const int b     = blockIdx.y;
    const int m0    = blockIdx.x << 5;
    const int tid   = threadIdx.x;
    const int g     = tid & 7;
    const int ml    = tid >> 3;
    const int mglob = m0 + ml;

    __shared__ float Ks[32][33];    // key tile     [n][j]
    __shared__ float Vs[256][36];   // value tile   [c][n]  (stride 36: 16B-aligned, conflict-free)
    __shared__ float Ps[32][36];    // probs        [m][n]

    // query vector (d=32) in registers
    float q[32];
    const float* kbase = g_K + ((size_t)b << 17) + mglob;
#pragma unroll
    for (int j = 0; j < 32; j++) q[j] = __ldg(&kbase[(size_t)j << 12]);

    float acc[32];
#pragma unroll
    for (int k = 0; k < 32; k++) acc[k] = 0.f;
    float run_max = -CUDART_INF_F;
    float l = 0.f;

    for (int n0 = 0; n0 < N_; n0 += 32) {
        // stage key tile [32 n][32 j]
        for (int idx = tid; idx < 1024; idx += 256) {
            int j = idx >> 5, nn = idx & 31;
            Ks[nn][j] = g_Q[((size_t)b << 17) + ((size_t)j << 12) + n0 + nn];
        }
        // stage value tile [256 c][32 n]
        for (int idx = tid; idx < 8192; idx += 256) {
            int c = idx >> 5, nn = idx & 31;
            Vs[c][nn] = g_V[(((size_t)(b << 8) + c) << 12) + n0 + nn];
        }
        __syncthreads();

        // S: this thread computes 4 scores (n = g + 8i)
        float s[4];
#pragma unroll
        for (int i = 0; i < 4; i++) {
            const int nn = g + (i << 3);
            float a0 = 0.f;
#pragma unroll
            for (int j = 0; j < 32; j++) a0 += q[j] * Ks[nn][j];
            s[i] = a0;
        }

        // online softmax over the 8-lane group owning row ml
        float tmax = fmaxf(fmaxf(s[0], s[1]), fmaxf(s[2], s[3]));
        tmax = fmaxf(tmax, __shfl_xor_sync(0xffffffffu, tmax, 1));
        tmax = fmaxf(tmax, __shfl_xor_sync(0xffffffffu, tmax, 2));
        tmax = fmaxf(tmax, __shfl_xor_sync(0xffffffffu, tmax, 4));
        const float nmax = fmaxf(run_max, tmax);
        const float corr = __expf(run_max - nmax);
        float psum = 0.f;
#pragma unroll
        for (int i = 0; i < 4; i++) {
            float p = __expf(s[i] - nmax);
            psum += p;
            Ps[ml][g + (i << 3)] = p;
        }
        psum += __shfl_xor_sync(0xffffffffu, psum, 1);
        psum += __shfl_xor_sync(0xffffffffu, psum, 2);
        psum += __shfl_xor_sync(0xffffffffu, psum, 4);
        l = l * corr + psum;
        run_max = nmax;
#pragma unroll
        for (int k = 0; k < 32; k++) acc[k] *= corr;
        __syncwarp();

        // PV: acc[k] += sum_n Ps[ml][n] * Vs[g+8k][n]
#pragma unroll
        for (int nq = 0; nq < 8; nq++) {
            const float4 p4 = *(const float4*)&Ps[ml][nq << 2];
#pragma unroll
            for (int k = 0; k < 32; k++) {
                const float4 v4 = *(const float4*)&Vs[g + (k << 3)][nq << 2];
                acc[k] += p4.x * v4.x + p4.y * v4.y + p4.z * v4.z + p4.w * v4.w;
            }
        }
        __syncthreads();
    }

    const float gam   = *gamma;
    const float inv_l = 1.0f / l;
#pragma unroll
    for (int k = 0; k < 32; k++) {
        const int c = g + (k << 3);
        const size_t idx = (((size_t)(b << 8) + c) << 12) + mglob;
        out[idx] = gam * acc[k] * inv_l + xin[idx];
    }
}

// ---------------------------------------------------------------------------
extern "C" void kernel_launch(void* const* d_in, const int* in_sizes, int n_in,
                              void* d_out, int out_size)
{
    const float* x     = (const float*)d_in[0];
    const float* Wq    = (const float*)d_in[1];
    const float* bq    = (const float*)d_in[2];
    const float* Wk    = (const float*)d_in[3];
    const float* bk    = (const float*)d_in[4];
    const float* Wv    = (const float*)d_in[5];
    const float* bv    = (const float*)d_in[6];
    const float* gamma = (const float*)d_in[7];
    float* out = (float*)d_out;

    // Projections into device-global scratch
    proj32_kernel<<<dim3(N_ / 128, B_), 256>>>(x, Wq, bq, /*which=*/0); // g_Q (FA keys)
    proj32_kernel<<<dim3(N_ / 128, B_), 256>>>(x, Wk, bk, /*which=*/1); // g_K (FA queries)
    projv_kernel<<<dim3(N_ / 64, C_ / 64, B_), 256>>>(x, Wv, bv);       // g_V

    // Flash attention + residual epilogue
    attn_kernel<<<dim3(N_ / 32, B_), 256>>>(x, gamma, out);
}

// round 4
// speedup vs baseline: 2.4346x; 2.4346x over previous
#include <cuda_runtime.h>
#include <math_constants.h>

#define B_   4
#define C_   256
#define C8_  32
#define N_   4096
#define BM   64
#define BN   32

// g_Q: FA "keys"    = Wq@x + bq, layout [b][j][n]
// g_K: FA "queries" = Wk@x + bk, layout [b][j][m]
// g_Vt: values transposed = Wv@x + bv, layout [b][n][c]
__device__ float g_Q [B_ * C8_ * N_];
__device__ float g_K [B_ * C8_ * N_];
__device__ float g_Vt[(size_t)B_ * N_ * C_];

// ---- packed f32x2 helpers -------------------------------------------------
__device__ __forceinline__ void fma2(unsigned long long& d,
                                     unsigned long long a, unsigned long long b) {
    asm("fma.rn.f32x2 %0, %1, %2, %0;" : "+l"(d) : "l"(a), "l"(b));
}
__device__ __forceinline__ void mul2(unsigned long long& d, unsigned long long a) {
    asm("mul.rn.f32x2 %0, %0, %1;" : "+l"(d) : "l"(a));
}
__device__ __forceinline__ unsigned long long pack2(float x, float y) {
    unsigned long long r;
    asm("mov.b64 %0, {%1, %2};" : "=l"(r) : "f"(x), "f"(y));
    return r;
}
__device__ __forceinline__ float2 unpack2(unsigned long long v) {
    float2 r;
    asm("mov.b64 {%0, %1}, %2;" : "=f"(r.x), "=f"(r.y) : "l"(v));
    return r;
}

// ---------------------------------------------------------------------------
// Q/K projection: out[b][j][n] = sum_c W[j][c]*x[b][c][n] + bias[j]
// ---------------------------------------------------------------------------
__global__ __launch_bounds__(256) void proj32_kernel(
    const float* __restrict__ x, const float* __restrict__ W,
    const float* __restrict__ bias, int which)
{
    float* __restrict__ out = which ? g_K : g_Q;
    const int b  = blockIdx.y;
    const int n0 = blockIdx.x * 128;
    __shared__ float Xs[32][132];
    __shared__ float Ws[32][33];
    const int tid = threadIdx.x;
    const int nl  = tid & 31;
    const int jg  = tid >> 5;

    float acc[4][4];
#pragma unroll
    for (int i = 0; i < 4; i++)
#pragma unroll
        for (int k = 0; k < 4; k++) acc[i][k] = 0.f;

    for (int c0 = 0; c0 < C_; c0 += 32) {
        for (int idx = tid; idx < 32 * 128; idx += 256) {
            int cc = idx >> 7, nn = idx & 127;
            Xs[cc][nn] = x[(((b << 8) + c0 + cc) << 12) + n0 + nn];
        }
        for (int idx = tid; idx < 1024; idx += 256) {
            int jj = idx >> 5, cc = idx & 31;
            Ws[jj][cc] = W[(jj << 8) + c0 + cc];
        }
        __syncthreads();
#pragma unroll
        for (int cc = 0; cc < 32; cc++) {
            float wv[4], xv[4];
#pragma unroll
            for (int ji = 0; ji < 4; ji++) wv[ji] = Ws[jg + 8 * ji][cc];
#pragma unroll
            for (int ni = 0; ni < 4; ni++) xv[ni] = Xs[cc][nl + 32 * ni];
#pragma unroll
            for (int ji = 0; ji < 4; ji++)
#pragma unroll
                for (int ni = 0; ni < 4; ni++) acc[ji][ni] += wv[ji] * xv[ni];
        }
        __syncthreads();
    }
#pragma unroll
    for (int ji = 0; ji < 4; ji++) {
        int j = jg + 8 * ji;
        float bj = bias[j];
#pragma unroll
        for (int ni = 0; ni < 4; ni++)
            out[(((b << 5) + j) << 12) + n0 + nl + 32 * ni] = acc[ji][ni] + bj;
    }
}

// ---------------------------------------------------------------------------
// V projection -> transposed g_Vt[b][n][c]
// ---------------------------------------------------------------------------
__global__ __launch_bounds__(256) void projv_kernel(
    const float* __restrict__ x, const float* __restrict__ W,
    const float* __restrict__ bias)
{
    const int b  = blockIdx.z;
    const int c0 = blockIdx.y * 64;
    const int n0 = blockIdx.x * 64;
    __shared__ float Xs[64][68];
    __shared__ float WsT[64][68];
    const int tid = threadIdx.x;
    const int tx = tid & 15;   // n quad
    const int ty = tid >> 4;   // c quad

    float acc[4][4];
#pragma unroll
    for (int i = 0; i < 4; i++)
#pragma unroll
        for (int k = 0; k < 4; k++) acc[i][k] = 0.f;

    for (int p0 = 0; p0 < C_; p0 += 64) {
        for (int idx = tid; idx < 4096; idx += 256) {
            int pp = idx >> 6, nn = idx & 63;
            Xs[pp][nn] = x[(((b << 8) + p0 + pp) << 12) + n0 + nn];
        }
        for (int idx = tid; idx < 4096; idx += 256) {
            int cc = idx >> 6, pp = idx & 63;
            WsT[pp][cc] = W[((c0 + cc) << 8) + p0 + pp];
        }
        __syncthreads();
#pragma unroll
        for (int pp = 0; pp < 64; pp++) {
            const float4 a  = *(const float4*)&WsT[pp][ty * 4];
            const float4 xb = *(const float4*)&Xs[pp][tx * 4];
            acc[0][0] += a.x * xb.x; acc[0][1] += a.x * xb.y;
            acc[0][2] += a.x * xb.z; acc[0][3] += a.x * xb.w;
            acc[1][0] += a.y * xb.x; acc[1][1] += a.y * xb.y;
            acc[1][2] += a.y * xb.z; acc[1][3] += a.y * xb.w;
            acc[2][0] += a.z * xb.x; acc[2][1] += a.z * xb.y;
            acc[2][2] += a.z * xb.z; acc[2][3] += a.z * xb.w;
            acc[3][0] += a.w * xb.x; acc[3][1] += a.w * xb.y;
            acc[3][2] += a.w * xb.z; acc[3][3] += a.w * xb.w;
        }
        __syncthreads();
    }
    const float b0 = bias[c0 + ty * 4 + 0];
    const float b1 = bias[c0 + ty * 4 + 1];
    const float b2 = bias[c0 + ty * 4 + 2];
    const float b3 = bias[c0 + ty * 4 + 3];
#pragma unroll
    for (int k = 0; k < 4; k++) {
        int n = n0 + tx * 4 + k;
        float4 r = make_float4(acc[0][k] + b0, acc[1][k] + b1,
                               acc[2][k] + b2, acc[3][k] + b3);
        *(float4*)&g_Vt[(((size_t)b << 12) + n) * C_ + c0 + ty * 4] = r;
    }
}

// ---------------------------------------------------------------------------
// Flash attention. BM=64 m/block, BN=32 n tile, f32x2 PV.
// PV: warp w owns m in [8w,8w+8); lane owns c = 4l..+4 and 128+4l..+4.
// S : warps 0-3 -> m = lane; warps 4-7 -> m = 32+lane; warp n-slice = (w&3)*8..+8.
// ---------------------------------------------------------------------------
struct AttnSmem {
    float Vs[BN][260];     // [n][c] value tile (float4-aligned rows)
    float Ps2[BN][132];    // probs duplicated: Ps2[n][2m]=Ps2[n][2m+1]=p(m,n)
    float Kn[BN][36];      // [n][j] key tile
    float Qs[BM][37];      // [m][j] query tile
    float Redmax[4][BM];
    float Redsum[4][BM];
    float rmax[BM];
    float lsum[BM];
    float corr_s[BM];
    float nmax_s[BM];
};

__global__ __launch_bounds__(256, 2) void attn_kernel(
    const float* __restrict__ xin, const float* __restrict__ gamma,
    float* __restrict__ out)
{
    extern __shared__ char smraw[];
    AttnSmem& sm = *reinterpret_cast<AttnSmem*>(smraw);

    const int b    = blockIdx.y;
    const int m0g  = blockIdx.x * BM;
    const int tid  = threadIdx.x;
    const int w    = tid >> 5;
    const int lane = tid & 31;
    const int pm0  = w * 8;              // PV m base
    const int colA = 4 * lane;
    const int colB = 128 + 4 * lane;
    const int grp  = w >> 2;             // S m-group
    const int nqw  = w & 3;              // S n-slice
    const int ms   = grp * 32 + lane;
    const int n_off = nqw * 8;

    for (int idx = tid; idx < BM * C8_; idx += 256) {
        int j = idx >> 6, m = idx & 63;
        sm.Qs[m][j] = g_K[(((size_t)b << 5) + j) * N_ + m0g + m];
    }
    if (tid < BM) {
        sm.rmax[tid]   = -CUDART_INF_F;
        sm.lsum[tid]   = 0.f;
        sm.corr_s[tid] = 1.f;
        sm.nmax_s[tid] = -CUDART_INF_F;
        sm.Redsum[0][tid] = 0.f; sm.Redsum[1][tid] = 0.f;
        sm.Redsum[2][tid] = 0.f; sm.Redsum[3][tid] = 0.f;
    }
    unsigned long long acc[8][4];
#pragma unroll
    for (int mi = 0; mi < 8; mi++)
#pragma unroll
        for (int j = 0; j < 4; j++) acc[mi][j] = 0ULL;
    __syncthreads();

    for (int n0 = 0; n0 < N_; n0 += BN) {
        // finalize previous tile's l, then stage tiles
        if (tid < BM) {
            sm.lsum[tid] = sm.lsum[tid] * sm.corr_s[tid] +
                (sm.Redsum[0][tid] + sm.Redsum[1][tid] +
                 sm.Redsum[2][tid] + sm.Redsum[3][tid]);
            sm.rmax[tid] = sm.nmax_s[tid];
        }
#pragma unroll
        for (int k = 0; k < 8; k++) {             // V tile (32 x 256)
            int idx = tid + k * 256;
            int n = idx >> 6, cq = (idx & 63) * 4;
            float4 v = *(const float4*)&g_Vt[(((size_t)b << 12) + n0 + n) * C_ + cq];
            *(float4*)&sm.Vs[n][cq] = v;
        }
#pragma unroll
        for (int k = 0; k < 4; k++) {             // key tile transposed
            int idx = tid + k * 256;
            int j = idx >> 5, n = idx & 31;
            sm.Kn[n][j] = g_Q[(((size_t)b << 5) + j) * N_ + n0 + n];
        }
        __syncthreads();

        // ---- S: s[i] = q(ms) . k(n_off+i) ----
        float s[8];
#pragma unroll
        for (int i = 0; i < 8; i++) s[i] = 0.f;
#pragma unroll
        for (int jq = 0; jq < 8; jq++) {
            const float q0 = sm.Qs[ms][jq * 4 + 0];
            const float q1 = sm.Qs[ms][jq * 4 + 1];
            const float q2 = sm.Qs[ms][jq * 4 + 2];
            const float q3 = sm.Qs[ms][jq * 4 + 3];
#pragma unroll
            for (int i = 0; i < 8; i++) {
                const float4 k4 = *(const float4*)&sm.Kn[n_off + i][jq * 4];
                s[i] = fmaf(q0, k4.x, fmaf(q1, k4.y, fmaf(q2, k4.z, fmaf(q3, k4.w, s[i]))));
            }
        }
        float tmax = fmaxf(fmaxf(fmaxf(s[0], s[1]), fmaxf(s[2], s[3])),
                           fmaxf(fmaxf(s[4], s[5]), fmaxf(s[6], s[7])));
        sm.Redmax[nqw][ms] = tmax;
        __syncthreads();

        // ---- softmax ----
        {
            const float gmax = fmaxf(fmaxf(sm.Redmax[0][ms], sm.Redmax[1][ms]),
                                     fmaxf(sm.Redmax[2][ms], sm.Redmax[3][ms]));
            const float rold = sm.rmax[ms];
            const float nmax = fmaxf(rold, gmax);
            float psum = 0.f;
#pragma unroll
            for (int i = 0; i < 8; i++) {
                const float p = __expf(s[i] - nmax);
                psum += p;
                *(float2*)&sm.Ps2[n_off + i][2 * ms] = make_float2(p, p);
            }
            sm.Redsum[nqw][ms] = psum;
            if (nqw == 0) {
                sm.corr_s[ms] = __expf(rold - nmax);
                sm.nmax_s[ms] = nmax;
            }
        }
        __syncthreads();

        // ---- PV: rescale + accumulate ----
#pragma unroll
        for (int mi = 0; mi < 8; mi++) {
            const float cs = sm.corr_s[pm0 + mi];
            const unsigned long long c2 = pack2(cs, cs);
            mul2(acc[mi][0], c2); mul2(acc[mi][1], c2);
            mul2(acc[mi][2], c2); mul2(acc[mi][3], c2);
        }
#pragma unroll 2
        for (int n = 0; n < BN; n++) {
            const ulonglong2 pa = *(const ulonglong2*)&sm.Ps2[n][2 * pm0];
            const ulonglong2 pb = *(const ulonglong2*)&sm.Ps2[n][2 * pm0 + 4];
            const ulonglong2 pc = *(const ulonglong2*)&sm.Ps2[n][2 * pm0 + 8];
            const ulonglong2 pd = *(const ulonglong2*)&sm.Ps2[n][2 * pm0 + 12];
            const unsigned long long p2[8] = {pa.x, pa.y, pb.x, pb.y,
                                              pc.x, pc.y, pd.x, pd.y};
            const ulonglong2 vA = *(const ulonglong2*)&sm.Vs[n][colA];
            const ulonglong2 vB = *(const ulonglong2*)&sm.Vs[n][colB];
#pragma unroll
            for (int mi = 0; mi < 8; mi++) {
                fma2(acc[mi][0], p2[mi], vA.x);
                fma2(acc[mi][1], p2[mi], vA.y);
                fma2(acc[mi][2], p2[mi], vB.x);
                fma2(acc[mi][3], p2[mi], vB.y);
            }
        }
        __syncthreads();
    }

    // final l
    if (tid < BM) {
        sm.lsum[tid] = sm.lsum[tid] * sm.corr_s[tid] +
            (sm.Redsum[0][tid] + sm.Redsum[1][tid] +
             sm.Redsum[2][tid] + sm.Redsum[3][tid]);
    }
    __syncthreads();

    // ---- epilogue: out[b][c][m] = gamma*acc/l + x ----
    const float gam = *gamma;
    float invl[8];
#pragma unroll
    for (int mi = 0; mi < 8; mi++) invl[mi] = 1.f / sm.lsum[pm0 + mi];

#pragma unroll
    for (int jj = 0; jj < 4; jj++) {
        const int cbase = ((jj >= 2) ? 128 : 0) + 4 * lane + ((jj & 1) * 2);
        float2 f[8];
#pragma unroll
        for (int mi = 0; mi < 8; mi++) f[mi] = unpack2(acc[mi][jj]);
#pragma unroll
        for (int h = 0; h < 2; h++) {
            const int c = cbase + h;
            const size_t base = (((size_t)b << 8) + c) * N_ + m0g + pm0;
            const float4 x0 = *(const float4*)&xin[base];
            const float4 x1 = *(const float4*)&xin[base + 4];
            float v[8];
#pragma unroll
            for (int mi = 0; mi < 8; mi++)
                v[mi] = gam * (h ? f[mi].y : f[mi].x) * invl[mi];
            float4 o0 = make_float4(v[0] + x0.x, v[1] + x0.y, v[2] + x0.z, v[3] + x0.w);
            float4 o1 = make_float4(v[4] + x1.x, v[5] + x1.y, v[6] + x1.z, v[7] + x1.w);
            *(float4*)&out[base]     = o0;
            *(float4*)&out[base + 4] = o1;
        }
    }
}

// ---------------------------------------------------------------------------
extern "C" void kernel_launch(void* const* d_in, const int* in_sizes, int n_in,
                              void* d_out, int out_size)
{
    const float* x     = (const float*)d_in[0];
    const float* Wq    = (const float*)d_in[1];
    const float* bq    = (const float*)d_in[2];
    const float* Wk    = (const float*)d_in[3];
    const float* bk    = (const float*)d_in[4];
    const float* Wv    = (const float*)d_in[5];
    const float* bv    = (const float*)d_in[6];
    const float* gamma = (const float*)d_in[7];
    float* out = (float*)d_out;

    const int smem_bytes = (int)sizeof(AttnSmem);
    static bool attr_set = false;
    if (!attr_set) {
        cudaFuncSetAttribute(attn_kernel,
                             cudaFuncAttributeMaxDynamicSharedMemorySize,
                             smem_bytes);
        attr_set = true;
    }

    proj32_kernel<<<dim3(N_ / 128, B_), 256>>>(x, Wq, bq, 0);       // g_Q
    proj32_kernel<<<dim3(N_ / 128, B_), 256>>>(x, Wk, bk, 1);       // g_K
    projv_kernel<<<dim3(N_ / 64, C_ / 64, B_), 256>>>(x, Wv, bv);   // g_Vt

    attn_kernel<<<dim3(N_ / BM, B_), 256, smem_bytes>>>(x, gamma, out);
}

// round 6
// speedup vs baseline: 5.7673x; 2.3689x over previous
#include <cuda_runtime.h>
#include <cstdint>

#define B_   4
#define C_   256
#define C8_  32
#define N_   4096

// ---------------- device scratch -------------------------------------------
__device__ float g_Qn[(size_t)B_ * N_ * C8_];   // [b][n][j]   GEMM1 A (row-major k)
__device__ float g_Km[(size_t)B_ * N_ * C8_];   // [b][m][j]   GEMM1 B (col-major k)
__device__ float g_V [(size_t)B_ * C_ * N_];    // [b][c][n]   GEMM2 B (col-major k)
__device__ float g_P [(size_t)B_ * N_ * N_];    // [b][m][n]   exp(S)
__device__ float g_l [(size_t)B_ * N_];         // row sums

// ---------------- helpers --------------------------------------------------
__device__ __forceinline__ uint32_t smem_u32(const void* p) {
    uint32_t a;
    asm("{ .reg .u64 t; cvta.to.shared.u64 t, %1; cvt.u32.u64 %0, t; }"
        : "=r"(a) : "l"(p));
    return a;
}
__device__ __forceinline__ uint32_t f2tf(float x) {
    uint32_t r;
    asm("cvt.rna.tf32.f32 %0, %1;" : "=r"(r) : "f"(x));
    return r;
}
__device__ __forceinline__ void mma8(float4& d, const uint32_t* a, const uint32_t* b) {
    asm("mma.sync.aligned.m16n8k8.row.col.f32.tf32.tf32.f32 "
        "{%0,%1,%2,%3}, {%4,%5,%6,%7}, {%8,%9}, {%0,%1,%2,%3};"
        : "+f"(d.x), "+f"(d.y), "+f"(d.z), "+f"(d.w)
        : "r"(a[0]), "r"(a[1]), "r"(a[2]), "r"(a[3]), "r"(b[0]), "r"(b[1]));
}
#define CP16(dst_u32, src_ptr) \
    asm volatile("cp.async.cg.shared.global [%0], [%1], 16;" \
                 :: "r"(dst_u32), "l"(src_ptr) : "memory")
#define CP_COMMIT() asm volatile("cp.async.commit_group;" ::: "memory")
#define CP_WAIT(n)  asm volatile("cp.async.wait_group %0;" :: "n"(n) : "memory")

// ---------------------------------------------------------------------------
// Q/K projection -> [b][n][j]
// ---------------------------------------------------------------------------
__global__ __launch_bounds__(256) void proj32_kernel(
    const float* __restrict__ x, const float* __restrict__ W,
    const float* __restrict__ bias, int which)
{
    float* __restrict__ out = which ? g_Km : g_Qn;
    const int b  = blockIdx.y;
    const int n0 = blockIdx.x * 128;
    __shared__ float Xs[32][132];
    __shared__ float Ws[32][33];
    const int tid = threadIdx.x;
    const int nl  = tid & 31;
    const int jg  = tid >> 5;

    float acc[4][4];
#pragma unroll
    for (int i = 0; i < 4; i++)
#pragma unroll
        for (int k = 0; k < 4; k++) acc[i][k] = 0.f;

    for (int c0 = 0; c0 < C_; c0 += 32) {
        for (int idx = tid; idx < 32 * 128; idx += 256) {
            int cc = idx >> 7, nn = idx & 127;
            Xs[cc][nn] = x[(((b << 8) + c0 + cc) << 12) + n0 + nn];
        }
        for (int idx = tid; idx < 1024; idx += 256) {
            int jj = idx >> 5, cc = idx & 31;
            Ws[jj][cc] = W[(jj << 8) + c0 + cc];
        }
        __syncthreads();
#pragma unroll
        for (int cc = 0; cc < 32; cc++) {
            float wv[4], xv[4];
#pragma unroll
            for (int ji = 0; ji < 4; ji++) wv[ji] = Ws[jg + 8 * ji][cc];
#pragma unroll
            for (int ni = 0; ni < 4; ni++) xv[ni] = Xs[cc][nl + 32 * ni];
#pragma unroll
            for (int ji = 0; ji < 4; ji++)
#pragma unroll
                for (int ni = 0; ni < 4; ni++) acc[ji][ni] += wv[ji] * xv[ni];
        }
        __syncthreads();
    }
#pragma unroll
    for (int ji = 0; ji < 4; ji++) {
        int j = jg + 8 * ji;
        float bj = bias[j];
#pragma unroll
        for (int ni = 0; ni < 4; ni++) {
            int n = n0 + nl + 32 * ni;
            out[(((size_t)b << 12) + n) * 32 + j] = acc[ji][ni] + bj;
        }
    }
}

// ---------------------------------------------------------------------------
// V projection -> g_V[b][c][n]
// ---------------------------------------------------------------------------
__global__ __launch_bounds__(256) void projv_kernel(
    const float* __restrict__ x, const float* __restrict__ W,
    const float* __restrict__ bias)
{
    const int b  = blockIdx.z;
    const int c0 = blockIdx.y * 64;
    const int n0 = blockIdx.x * 64;
    __shared__ float Xs[64][68];
    __shared__ float WsT[64][68];
    const int tid = threadIdx.x;
    const int tx = tid & 15;
    const int ty = tid >> 4;

    float acc[4][4];
#pragma unroll
    for (int i = 0; i < 4; i++)
#pragma unroll
        for (int k = 0; k < 4; k++) acc[i][k] = 0.f;

    for (int p0 = 0; p0 < C_; p0 += 64) {
        for (int idx = tid; idx < 4096; idx += 256) {
            int pp = idx >> 6, nn = idx & 63;
            Xs[pp][nn] = x[(((b << 8) + p0 + pp) << 12) + n0 + nn];
        }
        for (int idx = tid; idx < 4096; idx += 256) {
            int cc = idx >> 6, pp = idx & 63;
            WsT[pp][cc] = W[((c0 + cc) << 8) + p0 + pp];
        }
        __syncthreads();
#pragma unroll
        for (int pp = 0; pp < 64; pp++) {
            const float4 a  = *(const float4*)&WsT[pp][ty * 4];
            const float4 xb = *(const float4*)&Xs[pp][tx * 4];
            acc[0][0] += a.x * xb.x; acc[0][1] += a.x * xb.y;
            acc[0][2] += a.x * xb.z; acc[0][3] += a.x * xb.w;
            acc[1][0] += a.y * xb.x; acc[1][1] += a.y * xb.y;
            acc[1][2] += a.y * xb.z; acc[1][3] += a.y * xb.w;
            acc[2][0] += a.z * xb.x; acc[2][1] += a.z * xb.y;
            acc[2][2] += a.z * xb.z; acc[2][3] += a.z * xb.w;
            acc[3][0] += a.w * xb.x; acc[3][1] += a.w * xb.y;
            acc[3][2] += a.w * xb.z; acc[3][3] += a.w * xb.w;
        }
        __syncthreads();
    }
#pragma unroll
    for (int i = 0; i < 4; i++) {
        int c = c0 + ty * 4 + i;
        float bc = bias[c];
        float4 r = make_float4(acc[i][0] + bc, acc[i][1] + bc,
                               acc[i][2] + bc, acc[i][3] + bc);
        *(float4*)&g_V[(((size_t)(b << 8) + c) << 12) + n0 + tx * 4] = r;
    }
}

// ---------------------------------------------------------------------------
// GEMM1: D[n][m] = Qn[n,:] . Km[m,:]  (block 128n x 128m, K=32, mma.sync tf32)
// Epilogue: g_P[b][m][n] = exp(D)
// ---------------------------------------------------------------------------
__global__ __launch_bounds__(256) void gemm1_kernel()
{
    __shared__ float As[128][36];
    __shared__ float Bs[128][36];
    const int n0 = blockIdx.x * 128;
    const int m0 = blockIdx.y * 128;
    const int b  = blockIdx.z;
    const int tid = threadIdx.x;
    const int wid = tid >> 5;
    const int ln  = tid & 31;
    const int g   = ln >> 2;
    const int t   = ln & 3;
    const int mw  = wid & 1;    // n half (64)
    const int cw  = wid >> 1;   // m quarter (32)

    const size_t bq = ((size_t)b << 12);
#pragma unroll
    for (int i = 0; i < 4; i++) {
        int idx = tid + (i << 8);
        int r = idx >> 3, k4 = idx & 7;
        *(float4*)&As[r][k4 << 2] = *(const float4*)&g_Qn[(bq + n0 + r) * 32 + (k4 << 2)];
        *(float4*)&Bs[r][k4 << 2] = *(const float4*)&g_Km[(bq + m0 + r) * 32 + (k4 << 2)];
    }
    __syncthreads();

    float4 acc[4][4];
#pragma unroll
    for (int mt = 0; mt < 4; mt++)
#pragma unroll
        for (int ct = 0; ct < 4; ct++) acc[mt][ct] = make_float4(0.f, 0.f, 0.f, 0.f);

#pragma unroll
    for (int kk = 0; kk < 4; kk++) {
        const int k = kk << 3;
        uint32_t a[4][4], bb[4][2];
#pragma unroll
        for (int mt = 0; mt < 4; mt++) {
            const int rb = mw * 64 + mt * 16;
            a[mt][0] = f2tf(As[rb + g][k + t]);
            a[mt][1] = f2tf(As[rb + g + 8][k + t]);
            a[mt][2] = f2tf(As[rb + g][k + t + 4]);
            a[mt][3] = f2tf(As[rb + g + 8][k + t + 4]);
        }
#pragma unroll
        for (int ct = 0; ct < 4; ct++) {
            const int cb = cw * 32 + ct * 8;
            bb[ct][0] = f2tf(Bs[cb + g][k + t]);
            bb[ct][1] = f2tf(Bs[cb + g][k + t + 4]);
        }
#pragma unroll
        for (int mt = 0; mt < 4; mt++)
#pragma unroll
            for (int ct = 0; ct < 4; ct++) mma8(acc[mt][ct], a[mt], bb[ct]);
    }

    // epilogue: exp + scatter (8-lane contiguous n runs -> full 32B sectors)
    const size_t pb = ((size_t)b << 24);
#pragma unroll
    for (int mt = 0; mt < 4; mt++) {
        const int n = n0 + mw * 64 + mt * 16 + g;
#pragma unroll
        for (int ct = 0; ct < 4; ct++) {
            const int m = m0 + cw * 32 + ct * 8 + 2 * t;
            const float4 d = acc[mt][ct];
            g_P[pb + ((size_t)m << 12) + n]           = __expf(d.x);
            g_P[pb + ((size_t)(m + 1) << 12) + n]     = __expf(d.y);
            g_P[pb + ((size_t)m << 12) + n + 8]       = __expf(d.z);
            g_P[pb + ((size_t)(m + 1) << 12) + n + 8] = __expf(d.w);
        }
    }
}

// ---------------------------------------------------------------------------
// rowsum: g_l[r] = sum_n g_P[r][n]
// ---------------------------------------------------------------------------
__global__ __launch_bounds__(256) void rowsum_kernel()
{
    const int r = blockIdx.x * 8 + (threadIdx.x >> 5);
    const int ln = threadIdx.x & 31;
    const float4* row = (const float4*)(g_P + ((size_t)r << 12));
    float s = 0.f;
#pragma unroll 8
    for (int it = 0; it < 32; it++) {
        float4 v = row[ln + (it << 5)];
        s += v.x + v.y + v.z + v.w;
    }
    s += __shfl_xor_sync(0xffffffffu, s, 16);
    s += __shfl_xor_sync(0xffffffffu, s, 8);
    s += __shfl_xor_sync(0xffffffffu, s, 4);
    s += __shfl_xor_sync(0xffffffffu, s, 2);
    s += __shfl_xor_sync(0xffffffffu, s, 1);
    if (ln == 0) g_l[r] = s;
}

// ---------------------------------------------------------------------------
// GEMM2: D2[m][c] = sum_n P[m][n] V[c][n]  (block 128m x 256c, K=4096,
// 32-k chunks, cp.async double buffer, mma.sync tf32)
// Epilogue: out[b][c][m] = gamma*D2/l[m] + x[b][c][m]
// ---------------------------------------------------------------------------
#define A_ROWF 36
#define G2_AF  (128 * A_ROWF)          // floats per A buffer
#define G2_BF  (256 * A_ROWF)
#define G2_SMEM ((2 * (G2_AF + G2_BF)) * 4)

__global__ __launch_bounds__(256, 1) void gemm2_kernel(
    const float* __restrict__ xin, const float* __restrict__ gamma,
    float* __restrict__ out)
{
    extern __shared__ float sm2[];
    float* Abuf[2] = { sm2,            sm2 + G2_AF };
    float* Bbuf[2] = { sm2 + 2 * G2_AF, sm2 + 2 * G2_AF + G2_BF };
    const uint32_t smbase = smem_u32(sm2);
    const uint32_t Aaddr[2] = { smbase, smbase + G2_AF * 4 };
    const uint32_t Baddr[2] = { smbase + 2 * G2_AF * 4, smbase + (2 * G2_AF + G2_BF) * 4 };

    const int m0 = blockIdx.x * 128;
    const int b  = blockIdx.y;
    const int tid = threadIdx.x;
    const int wid = tid >> 5;
    const int ln  = tid & 31;
    const int g   = ln >> 2;
    const int t   = ln & 3;
    const int mw  = wid & 1;    // 64 m
    const int cw  = wid >> 1;   // 64 c

    const size_t pbase = ((size_t)b << 24) + ((size_t)m0 << 12);
    const size_t vbase = (size_t)b << 20;      // b * C_ * N_

    const int ar = tid >> 3, ak = tid & 7;     // A: 128 rows, 8 float4/row (4 iters)
    // stage chunk ch into buffer sel
    auto stage = [&](int ch, int sel) {
        const int nk = ch << 5;
#pragma unroll
        for (int i = 0; i < 4; i++) {
            int r = ar + (i << 5);
            CP16(Aaddr[sel] + (r * A_ROWF + (ak << 2)) * 4,
                 g_P + pbase + ((size_t)r << 12) + nk + (ak << 2));
        }
#pragma unroll
        for (int i = 0; i < 8; i++) {
            int r = ar + (i << 5);
            CP16(Baddr[sel] + (r * A_ROWF + (ak << 2)) * 4,
                 g_V + vbase + ((size_t)r << 12) + nk + (ak << 2));
        }
    };

    float4 acc[4][8];
#pragma unroll
    for (int mt = 0; mt < 4; mt++)
#pragma unroll
        for (int ct = 0; ct < 8; ct++) acc[mt][ct] = make_float4(0.f, 0.f, 0.f, 0.f);

    stage(0, 0);
    CP_COMMIT();

    for (int ch = 0; ch < 128; ch++) {
        const int sel = ch & 1;
        if (ch + 1 < 128) { stage(ch + 1, sel ^ 1); CP_COMMIT(); CP_WAIT(1); }
        else              { CP_WAIT(0); }
        __syncthreads();

        const float* As = Abuf[sel];
        const float* Bs = Bbuf[sel];
#pragma unroll
        for (int kk = 0; kk < 4; kk++) {
            const int k = kk << 3;
            uint32_t a[4][4], bb[8][2];
#pragma unroll
            for (int mt = 0; mt < 4; mt++) {
                const int rb = mw * 64 + mt * 16;
                a[mt][0] = f2tf(As[(rb + g) * A_ROWF + k + t]);
                a[mt][1] = f2tf(As[(rb + g + 8) * A_ROWF + k + t]);
                a[mt][2] = f2tf(As[(rb + g) * A_ROWF + k + t + 4]);
                a[mt][3] = f2tf(As[(rb + g + 8) * A_ROWF + k + t + 4]);
            }
#pragma unroll
            for (int ct = 0; ct < 8; ct++) {
                const int cb = cw * 64 + ct * 8;
                bb[ct][0] = f2tf(Bs[(cb + g) * A_ROWF + k + t]);
                bb[ct][1] = f2tf(Bs[(cb + g) * A_ROWF + k + t + 4]);
            }
#pragma unroll
            for (int mt = 0; mt < 4; mt++)
#pragma unroll
                for (int ct = 0; ct < 8; ct++) mma8(acc[mt][ct], a[mt], bb[ct]);
        }
        __syncthreads();
    }

    // epilogue
    const float gam = *gamma;
    float il0[4], il1[4];
#pragma unroll
    for (int mt = 0; mt < 4; mt++) {
        const int mm = m0 + mw * 64 + mt * 16 + g;
        il0[mt] = 1.0f / g_l[((size_t)b << 12) + mm];
        il1[mt] = 1.0f / g_l[((size_t)b << 12) + mm + 8];
    }
#pragma unroll
    for (int mt = 0; mt < 4; mt++) {
        const int m = m0 + mw * 64 + mt * 16 + g;
#pragma unroll
        for (int ct = 0; ct < 8; ct++) {
            const int c = cw * 64 + ct * 8 + 2 * t;
            const float4 d = acc[mt][ct];
            const size_t i00 = (((size_t)(b << 8) + c) << 12) + m;
            const size_t i01 = i00 + N_;           // c+1
            out[i00]     = gam * d.x * il0[mt] + xin[i00];
            out[i01]     = gam * d.y * il0[mt] + xin[i01];
            out[i00 + 8] = gam * d.z * il1[mt] + xin[i00 + 8];
            out[i01 + 8] = gam * d.w * il1[mt] + xin[i01 + 8];
        }
    }
}

// ---------------------------------------------------------------------------
extern "C" void kernel_launch(void* const* d_in, const int* in_sizes, int n_in,
                              void* d_out, int out_size)
{
    const float* x     = (const float*)d_in[0];
    const float* Wq    = (const float*)d_in[1];
    const float* bq    = (const float*)d_in[2];
    const float* Wk    = (const float*)d_in[3];
    const float* bk    = (const float*)d_in[4];
    const float* Wv    = (const float*)d_in[5];
    const float* bv    = (const float*)d_in[6];
    const float* gamma = (const float*)d_in[7];
    float* out = (float*)d_out;

    static bool attr_set = false;
    if (!attr_set) {
        cudaFuncSetAttribute(gemm2_kernel,
            cudaFuncAttributeMaxDynamicSharedMemorySize, G2_SMEM);
        attr_set = true;
    }

    proj32_kernel<<<dim3(N_ / 128, B_), 256>>>(x, Wq, bq, 0);        // g_Qn
    proj32_kernel<<<dim3(N_ / 128, B_), 256>>>(x, Wk, bk, 1);        // g_Km
    projv_kernel<<<dim3(N_ / 64, C_ / 64, B_), 256>>>(x, Wv, bv);    // g_V

    gemm1_kernel<<<dim3(N_ / 128, N_ / 128, B_), 256>>>();           // g_P
    rowsum_kernel<<<(B_ * N_) / 8, 256>>>();                         // g_l
    gemm2_kernel<<<dim3(N_ / 128, B_), 256, G2_SMEM>>>(x, gamma, out);
}

// round 7
// speedup vs baseline: 8.0248x; 1.3914x over previous
#include <cuda_runtime.h>
#include <cstdint>

#define B_   4
#define C_   256
#define N_   4096

// ---------------- device scratch (chunk-major, swizzled) --------------------
// g_Qn/g_Km: [b][n][j'] with j' = j ^ ((n&7)*4)           (16B rows of 32 fl)
// g_V:  [b][ch][c][nn'] nn' = (n&31) ^ ((c&7)*4), ch=n>>5 (tile 256x32 contig)
// g_P:  [b][ch][m][nn'] nn' = (n&31) ^ ((m&7)*4)          (tile 128x32 contig)
__device__ float g_Qn[(size_t)B_ * N_ * 32];
__device__ float g_Km[(size_t)B_ * N_ * 32];
__device__ float g_V [(size_t)B_ * 128 * C_ * 32];
__device__ float g_P [(size_t)B_ * 128 * N_ * 32];
__device__ float g_l [B_ * N_];

// ---------------- helpers --------------------------------------------------
__device__ __forceinline__ uint32_t smem_u32(const void* p) {
    uint32_t a;
    asm("{ .reg .u64 t; cvta.to.shared.u64 t, %1; cvt.u32.u64 %0, t; }"
        : "=r"(a) : "l"(p));
    return a;
}
__device__ __forceinline__ float f2tf(float x) {
    uint32_t r;
    asm("cvt.rna.tf32.f32 %0, %1;" : "=r"(r) : "f"(x));
    return __uint_as_float(r);
}
__device__ __forceinline__ void mma8(float4& d, const uint32_t* a, const uint32_t* b) {
    asm("mma.sync.aligned.m16n8k8.row.col.f32.tf32.tf32.f32 "
        "{%0,%1,%2,%3}, {%4,%5,%6,%7}, {%8,%9}, {%0,%1,%2,%3};"
        : "+f"(d.x), "+f"(d.y), "+f"(d.z), "+f"(d.w)
        : "r"(a[0]), "r"(a[1]), "r"(a[2]), "r"(a[3]), "r"(b[0]), "r"(b[1]));
}
#define MBAR_INIT(a, n) \
    asm volatile("mbarrier.init.shared.b64 [%0], %1;" :: "r"(a), "r"(n) : "memory")
#define MBAR_EXPECT(a, tx) \
    asm volatile("mbarrier.arrive.expect_tx.shared.b64 _, [%0], %1;" \
                 :: "r"(a), "r"(tx) : "memory")
#define MBAR_WAIT(a, par) do {                                                \
    uint32_t _m = (a), _p = (par), _d;                                        \
    asm volatile("{\n\t.reg .pred p;\n\t"                                     \
        "mbarrier.try_wait.parity.acquire.cta.shared::cta.b64 p, [%1], %2;\n\t" \
        "selp.b32 %0, 1, 0, p;\n\t}" : "=r"(_d) : "r"(_m), "r"(_p) : "memory"); \
    if (!_d) {                                                                \
        asm volatile("{\n\t.reg .pred P1;\n\t"                                \
            "WL_%=:\n\t"                                                      \
            "mbarrier.try_wait.parity.acquire.cta.shared::cta.b64 P1, [%0], %1, 0x989680;\n\t" \
            "@P1 bra.uni WD_%=;\n\t"                                          \
            "bra.uni WL_%=;\n\t"                                              \
            "WD_%=:\n\t}" :: "r"(_m), "r"(_p) : "memory");                    \
    }                                                                         \
} while (0)
#define BULK_G2S(dst, src, bytes, mbar) \
    asm volatile("cp.async.bulk.shared::cta.global.mbarrier::complete_tx::bytes " \
                 "[%0], [%1], %2, [%3];" \
                 :: "r"(dst), "l"(src), "r"(bytes), "r"(mbar) : "memory")
#define FENCE_ASYNC() asm volatile("fence.proxy.async.shared::cta;" ::: "memory")

// ---------------------------------------------------------------------------
__global__ void zero_l_kernel() {
    g_l[blockIdx.x * 512 + threadIdx.x] = 0.f;
}

// ---------------------------------------------------------------------------
// Q/K projection -> [b][n][j'] (tf32-rounded, swizzled)
// ---------------------------------------------------------------------------
__global__ __launch_bounds__(256) void proj32_kernel(
    const float* __restrict__ x, const float* __restrict__ W,
    const float* __restrict__ bias, int which)
{
    float* __restrict__ out = which ? g_Km : g_Qn;
    const int b  = blockIdx.y;
    const int n0 = blockIdx.x * 128;
    __shared__ float Xs[32][132];
    __shared__ float Ws[32][33];
    const int tid = threadIdx.x;
    const int nl  = tid & 31;
    const int jg  = tid >> 5;

    float acc[4][4];
#pragma unroll
    for (int i = 0; i < 4; i++)
#pragma unroll
        for (int k = 0; k < 4; k++) acc[i][k] = 0.f;

    for (int c0 = 0; c0 < C_; c0 += 32) {
        for (int idx = tid; idx < 32 * 128; idx += 256) {
            int cc = idx >> 7, nn = idx & 127;
            Xs[cc][nn] = x[(((b << 8) + c0 + cc) << 12) + n0 + nn];
        }
        for (int idx = tid; idx < 1024; idx += 256) {
            int jj = idx >> 5, cc = idx & 31;
            Ws[jj][cc] = W[(jj << 8) + c0 + cc];
        }
        __syncthreads();
#pragma unroll
        for (int cc = 0; cc < 32; cc++) {
            float wv[4], xv[4];
#pragma unroll
            for (int ji = 0; ji < 4; ji++) wv[ji] = Ws[jg + 8 * ji][cc];
#pragma unroll
            for (int ni = 0; ni < 4; ni++) xv[ni] = Xs[cc][nl + 32 * ni];
#pragma unroll
            for (int ji = 0; ji < 4; ji++)
#pragma unroll
                for (int ni = 0; ni < 4; ni++) acc[ji][ni] += wv[ji] * xv[ni];
        }
        __syncthreads();
    }
#pragma unroll
    for (int ji = 0; ji < 4; ji++) {
        int j = jg + 8 * ji;
        float bj = bias[j];
#pragma unroll
        for (int ni = 0; ni < 4; ni++) {
            int n = n0 + nl + 32 * ni;
            out[(((size_t)b << 12) + n) * 32 + (j ^ ((n & 7) << 2))] =
                f2tf(acc[ji][ni] + bj);
        }
    }
}

// ---------------------------------------------------------------------------
// V projection -> g_V chunk-major swizzled, tf32-rounded
// ---------------------------------------------------------------------------
__global__ __launch_bounds__(256) void projv_kernel(
    const float* __restrict__ x, const float* __restrict__ W,
    const float* __restrict__ bias)
{
    const int b  = blockIdx.z;
    const int c0 = blockIdx.y * 64;
    const int n0 = blockIdx.x * 64;
    __shared__ float Xs[64][68];
    __shared__ float WsT[64][68];
    const int tid = threadIdx.x;
    const int tx = tid & 15;
    const int ty = tid >> 4;

    float acc[4][4];
#pragma unroll
    for (int i = 0; i < 4; i++)
#pragma unroll
        for (int k = 0; k < 4; k++) acc[i][k] = 0.f;

    for (int p0 = 0; p0 < C_; p0 += 64) {
        for (int idx = tid; idx < 4096; idx += 256) {
            int pp = idx >> 6, nn = idx & 63;
            Xs[pp][nn] = x[(((b << 8) + p0 + pp) << 12) + n0 + nn];
        }
        for (int idx = tid; idx < 4096; idx += 256) {
            int cc = idx >> 6, pp = idx & 63;
            WsT[pp][cc] = W[((c0 + cc) << 8) + p0 + pp];
        }
        __syncthreads();
#pragma unroll
        for (int pp = 0; pp < 64; pp++) {
            const float4 a  = *(const float4*)&WsT[pp][ty * 4];
            const float4 xb = *(const float4*)&Xs[pp][tx * 4];
            acc[0][0] += a.x * xb.x; acc[0][1] += a.x * xb.y;
            acc[0][2] += a.x * xb.z; acc[0][3] += a.x * xb.w;
            acc[1][0] += a.y * xb.x; acc[1][1] += a.y * xb.y;
            acc[1][2] += a.y * xb.z; acc[1][3] += a.y * xb.w;
            acc[2][0] += a.z * xb.x; acc[2][1] += a.z * xb.y;
            acc[2][2] += a.z * xb.z; acc[2][3] += a.z * xb.w;
            acc[3][0] += a.w * xb.x; acc[3][1] += a.w * xb.y;
            acc[3][2] += a.w * xb.z; acc[3][3] += a.w * xb.w;
        }
        __syncthreads();
    }
    const int n = n0 + tx * 4;
    const int ch = n >> 5;
    const int nn = n & 31;
#pragma unroll
    for (int i = 0; i < 4; i++) {
        int c = c0 + ty * 4 + i;
        float bc = bias[c];
        float4 r = make_float4(f2tf(acc[i][0] + bc), f2tf(acc[i][1] + bc),
                               f2tf(acc[i][2] + bc), f2tf(acc[i][3] + bc));
        size_t base = ((((size_t)b * 128 + ch) * C_) + c) * 32 + (nn ^ ((c & 7) << 2));
        *(float4*)&g_V[base] = r;
    }
}

// ---------------------------------------------------------------------------
// GEMM1: D[n][m] = Qn[n,:] . Km[m,:]  (128n x 128m, K=32, mma.sync tf32)
// Epilogue: g_P = tf32(exp(D)) in chunk layout; rowsum fused via atomics.
// ---------------------------------------------------------------------------
__global__ __launch_bounds__(256) void gemm1_kernel()
{
    __shared__ float As[128 * 32];
    __shared__ float Bs[128 * 32];
    __shared__ __align__(8) unsigned long long s_mbar;
    const int n0 = blockIdx.x * 128;
    const int m0 = blockIdx.y * 128;
    const int b  = blockIdx.z;
    const int tid = threadIdx.x;
    const int wid = tid >> 5;
    const int ln  = tid & 31;
    const int g   = ln >> 2;
    const int t   = ln & 3;
    const int mw  = wid & 1;    // n half (64)
    const int cw  = wid >> 1;   // m quarter (32)

    const uint32_t mbar = smem_u32(&s_mbar);
    if (tid == 0) {
        MBAR_INIT(mbar, 1);
        FENCE_ASYNC();
        MBAR_EXPECT(mbar, 32768);
        BULK_G2S(smem_u32(As), g_Qn + (((size_t)b << 12) + n0) * 32, 16384, mbar);
        BULK_G2S(smem_u32(Bs), g_Km + (((size_t)b << 12) + m0) * 32, 16384, mbar);
    }
    __syncthreads();
    MBAR_WAIT(mbar, 0);

    const uint32_t* Au = (const uint32_t*)As;
    const uint32_t* Bu = (const uint32_t*)Bs;
    float4 acc[4][4];
#pragma unroll
    for (int mt = 0; mt < 4; mt++)
#pragma unroll
        for (int ct = 0; ct < 4; ct++) acc[mt][ct] = make_float4(0.f, 0.f, 0.f, 0.f);

    const uint32_t sx = (uint32_t)(g << 2);
#pragma unroll
    for (int kk = 0; kk < 4; kk++) {
        const int k = kk << 3;
        uint32_t a[4][4], bb[4][2];
#pragma unroll
        for (int mt = 0; mt < 4; mt++) {
            const int rb = mw * 64 + mt * 16;
            a[mt][0] = Au[(rb + g) * 32 + ((k + t) ^ sx)];
            a[mt][1] = Au[(rb + g + 8) * 32 + ((k + t) ^ sx)];
            a[mt][2] = Au[(rb + g) * 32 + ((k + t + 4) ^ sx)];
            a[mt][3] = Au[(rb + g + 8) * 32 + ((k + t + 4) ^ sx)];
        }
#pragma unroll
        for (int ct = 0; ct < 4; ct++) {
            const int cb = cw * 32 + ct * 8;
            bb[ct][0] = Bu[(cb + g) * 32 + ((k + t) ^ sx)];
            bb[ct][1] = Bu[(cb + g) * 32 + ((k + t + 4) ^ sx)];
        }
#pragma unroll
        for (int mt = 0; mt < 4; mt++)
#pragma unroll
            for (int ct = 0; ct < 4; ct++) mma8(acc[mt][ct], a[mt], bb[ct]);
    }

    // epilogue: exp + tf32 round + chunked store + fused rowsum
    float sum0[4], sum1[4];
#pragma unroll
    for (int ct = 0; ct < 4; ct++) { sum0[ct] = 0.f; sum1[ct] = 0.f; }

#pragma unroll
    for (int mt = 0; mt < 4; mt++) {
        const int n = n0 + mw * 64 + mt * 16 + g;
        const int ch = n >> 5, nn = n & 31;
        const size_t tb = (((size_t)b * 128 + ch) << 12) * 32;   // chunk base
#pragma unroll
        for (int ct = 0; ct < 4; ct++) {
            const int m = m0 + cw * 32 + ct * 8 + 2 * t;
            const float4 d = acc[mt][ct];
            const float px = f2tf(__expf(d.x));
            const float py = f2tf(__expf(d.y));
            const float pz = f2tf(__expf(d.z));
            const float pw = f2tf(__expf(d.w));
            const uint32_t sm0 = (uint32_t)((m & 7) << 2);
            const uint32_t sm1 = (uint32_t)(((m + 1) & 7) << 2);
            g_P[tb + (size_t)m * 32 + (nn ^ sm0)]           = px;
            g_P[tb + (size_t)(m + 1) * 32 + (nn ^ sm1)]     = py;
            g_P[tb + (size_t)m * 32 + ((nn + 8) ^ sm0)]     = pz;
            g_P[tb + (size_t)(m + 1) * 32 + ((nn + 8) ^ sm1)] = pw;
            sum0[ct] += px + pz;
            sum1[ct] += py + pw;
        }
    }
#pragma unroll
    for (int ct = 0; ct < 4; ct++) {
#pragma unroll
        for (int d = 4; d < 32; d <<= 1) {
            sum0[ct] += __shfl_xor_sync(0xffffffffu, sum0[ct], d);
            sum1[ct] += __shfl_xor_sync(0xffffffffu, sum1[ct], d);
        }
    }
    if (g == 0) {
#pragma unroll
        for (int ct = 0; ct < 4; ct++) {
            const int m = m0 + cw * 32 + ct * 8 + 2 * t;
            atomicAdd(&g_l[(b << 12) + m],     sum0[ct]);
            atomicAdd(&g_l[(b << 12) + m + 1], sum1[ct]);
        }
    }
}

// ---------------------------------------------------------------------------
// GEMM2: D2[m][c] = sum_n P[m][n] V[c][n]  (128m x 256c, K=4096, 32-k chunks,
// 3-stage cp.async.bulk pipeline). Epilogue: out = gamma*D2/l + x.
// ---------------------------------------------------------------------------
#define NSTG 3
#define STG_BYTES (16384 + 32768)
#define G2_SMEM (NSTG * STG_BYTES)

__global__ __launch_bounds__(256, 1) void gemm2_kernel(
    const float* __restrict__ xin, const float* __restrict__ gamma,
    float* __restrict__ out)
{
    extern __shared__ __align__(1024) char sm2[];
    __shared__ __align__(8) unsigned long long s_mb[NSTG];

    const int m0 = blockIdx.x * 128;
    const int b  = blockIdx.y;
    const int tid = threadIdx.x;
    const int wid = tid >> 5;
    const int ln  = tid & 31;
    const int g   = ln >> 2;
    const int t   = ln & 3;
    const int mw  = wid & 1;    // 64 m
    const int cw  = wid >> 1;   // 64 c

    uint32_t mb[NSTG];
#pragma unroll
    for (int s = 0; s < NSTG; s++) mb[s] = smem_u32(&s_mb[s]);
    if (tid == 0) {
#pragma unroll
        for (int s = 0; s < NSTG; s++) MBAR_INIT(mb[s], 1);
        FENCE_ASYNC();
    }
    __syncthreads();

    // P chunk tile base: g_P + ((b*128+ch)*4096 + m0)*32 ; 16 KB
    // V chunk tile base: g_V + ((b*128+ch)*256)*32       ; 32 KB
    const float* Pg = g_P + ((size_t)b * 128 << 12) * 32 + ((size_t)m0 * 32);
    const float* Vg = g_V + ((size_t)b * 128 * C_) * 32;

    auto issue = [&](int ch, int st) {
        MBAR_EXPECT(mb[st], STG_BYTES);
        const uint32_t dst = smem_u32(sm2) + st * STG_BYTES;
        BULK_G2S(dst,         Pg + ((size_t)ch << 12) * 32, 16384, mb[st]);
        BULK_G2S(dst + 16384, Vg + ((size_t)ch * C_) * 32, 32768, mb[st]);
    };

    if (tid == 0) {
#pragma unroll
        for (int s = 0; s < NSTG; s++) issue(s, s);
    }

    float4 acc[4][8];
#pragma unroll
    for (int mt = 0; mt < 4; mt++)
#pragma unroll
        for (int ct = 0; ct < 8; ct++) acc[mt][ct] = make_float4(0.f, 0.f, 0.f, 0.f);

    const uint32_t sx = (uint32_t)(g << 2);
    int ph[NSTG];
#pragma unroll
    for (int s = 0; s < NSTG; s++) ph[s] = 0;

    for (int ch = 0; ch < 128; ch++) {
        const int st = ch % NSTG;
        MBAR_WAIT(mb[st], ph[st]);
        ph[st] ^= 1;

        const uint32_t* Pu = (const uint32_t*)(sm2 + st * STG_BYTES);
        const uint32_t* Vu = (const uint32_t*)(sm2 + st * STG_BYTES + 16384);
#pragma unroll
        for (int kk = 0; kk < 4; kk++) {
            const int k = kk << 3;
            uint32_t a[4][4], bb[8][2];
#pragma unroll
            for (int mt = 0; mt < 4; mt++) {
                const int rb = mw * 64 + mt * 16;
                a[mt][0] = Pu[(rb + g) * 32 + ((k + t) ^ sx)];
                a[mt][1] = Pu[(rb + g + 8) * 32 + ((k + t) ^ sx)];
                a[mt][2] = Pu[(rb + g) * 32 + ((k + t + 4) ^ sx)];
                a[mt][3] = Pu[(rb + g + 8) * 32 + ((k + t + 4) ^ sx)];
            }
#pragma unroll
            for (int ct = 0; ct < 8; ct++) {
                const int cb = cw * 64 + ct * 8;
                bb[ct][0] = Vu[(cb + g) * 32 + ((k + t) ^ sx)];
                bb[ct][1] = Vu[(cb + g) * 32 + ((k + t + 4) ^ sx)];
            }
#pragma unroll
            for (int mt = 0; mt < 4; mt++)
#pragma unroll
                for (int ct = 0; ct < 8; ct++) mma8(acc[mt][ct], a[mt], bb[ct]);
        }
        __syncthreads();
        if (tid == 0 && ch + NSTG < 128) issue(ch + NSTG, st);
    }

    // epilogue
    const float gam = *gamma;
    float il0[4], il1[4];
#pragma unroll
    for (int mt = 0; mt < 4; mt++) {
        const int mm = m0 + mw * 64 + mt * 16 + g;
        il0[mt] = 1.0f / g_l[(b << 12) + mm];
        il1[mt] = 1.0f / g_l[(b << 12) + mm + 8];
    }
#pragma unroll
    for (int mt = 0; mt < 4; mt++) {
        const int m = m0 + mw * 64 + mt * 16 + g;
#pragma unroll
        for (int ct = 0; ct < 8; ct++) {
            const int c = cw * 64 + ct * 8 + 2 * t;
            const float4 d = acc[mt][ct];
            const size_t i00 = (((size_t)(b << 8) + c) << 12) + m;
            const size_t i01 = i00 + N_;
            out[i00]     = gam * d.x * il0[mt] + xin[i00];
            out[i01]     = gam * d.y * il0[mt] + xin[i01];
            out[i00 + 8] = gam * d.z * il1[mt] + xin[i00 + 8];
            out[i01 + 8] = gam * d.w * il1[mt] + xin[i01 + 8];
        }
    }
}

// ---------------------------------------------------------------------------
extern "C" void kernel_launch(void* const* d_in, const int* in_sizes, int n_in,
                              void* d_out, int out_size)
{
    const float* x     = (const float*)d_in[0];
    const float* Wq    = (const float*)d_in[1];
    const float* bq    = (const float*)d_in[2];
    const float* Wk    = (const float*)d_in[3];
    const float* bk    = (const float*)d_in[4];
    const float* Wv    = (const float*)d_in[5];
    const float* bv    = (const float*)d_in[6];
    const float* gamma = (const float*)d_in[7];
    float* out = (float*)d_out;

    static bool attr_set = false;
    if (!attr_set) {
        cudaFuncSetAttribute(gemm2_kernel,
            cudaFuncAttributeMaxDynamicSharedMemorySize, G2_SMEM);
        attr_set = true;
    }

    zero_l_kernel<<<(B_ * N_) / 512, 512>>>();
    proj32_kernel<<<dim3(N_ / 128, B_), 256>>>(x, Wq, bq, 0);        // g_Qn
    proj32_kernel<<<dim3(N_ / 128, B_), 256>>>(x, Wk, bk, 1);        // g_Km
    projv_kernel<<<dim3(N_ / 64, C_ / 64, B_), 256>>>(x, Wv, bv);    // g_V

    gemm1_kernel<<<dim3(N_ / 128, N_ / 128, B_), 256>>>();           // g_P + g_l
    gemm2_kernel<<<dim3(N_ / 128, B_), 256, G2_SMEM>>>(x, gamma, out);
}

// round 9
// speedup vs baseline: 12.1851x; 1.5184x over previous
#include <cuda_runtime.h>
#include <cstdint>

#define B_   4
#define C_   256
#define N_   4096

// ---------------- device scratch -------------------------------------------
// g_Qn/g_Km: [b][n][j'] j' = j ^ ((n&7)<<2)                 (32-float rows)
// g_P: [b][ch64][m][nn'] nn' = (n&63) ^ ((m&7)<<2)          (64-float rows)
// g_V: [b][ch64][c][nn'] nn' = (n&63) ^ ((c&7)<<2)
__device__ float g_Qn[(size_t)B_ * N_ * 32];
__device__ float g_Km[(size_t)B_ * N_ * 32];
__device__ float g_P [(size_t)B_ * 64 * N_ * 64];
__device__ float g_V [(size_t)B_ * 64 * C_ * 64];
__device__ float g_l [B_ * N_];

// ---------------- helpers --------------------------------------------------
__device__ __forceinline__ uint32_t smem_u32(const void* p) {
    uint32_t a;
    asm("{ .reg .u64 t; cvta.to.shared.u64 t, %1; cvt.u32.u64 %0, t; }"
        : "=r"(a) : "l"(p));
    return a;
}
__device__ __forceinline__ float f2tf(float x) {
    uint32_t r;
    asm("cvt.rna.tf32.f32 %0, %1;" : "=r"(r) : "f"(x));
    return __uint_as_float(r);
}
__device__ __forceinline__ void mma8(float4& d, const uint32_t* a, const uint32_t* b) {
    asm("mma.sync.aligned.m16n8k8.row.col.f32.tf32.tf32.f32 "
        "{%0,%1,%2,%3}, {%4,%5,%6,%7}, {%8,%9}, {%0,%1,%2,%3};"
        : "+f"(d.x), "+f"(d.y), "+f"(d.z), "+f"(d.w)
        : "r"(a[0]), "r"(a[1]), "r"(a[2]), "r"(a[3]), "r"(b[0]), "r"(b[1]));
}
#define MBAR_INIT(a, n) \
    asm volatile("mbarrier.init.shared.b64 [%0], %1;" :: "r"(a), "r"(n) : "memory")
#define MBAR_EXPECT(a, tx) \
    asm volatile("mbarrier.arrive.expect_tx.shared.b64 _, [%0], %1;" \
                 :: "r"(a), "r"(tx) : "memory")
#define MBAR_WAIT(a, par) do {                                                \
    uint32_t _m = (a), _p = (par), _d;                                        \
    asm volatile("{\n\t.reg .pred p;\n\t"                                     \
        "mbarrier.try_wait.parity.acquire.cta.shared::cta.b64 p, [%1], %2;\n\t" \
        "selp.b32 %0, 1, 0, p;\n\t}" : "=r"(_d) : "r"(_m), "r"(_p) : "memory"); \
    if (!_d) {                                                                \
        asm volatile("{\n\t.reg .pred P1;\n\t"                                \
            "WL_%=:\n\t"                                                      \
            "mbarrier.try_wait.parity.acquire.cta.shared::cta.b64 P1, [%0], %1, 0x989680;\n\t" \
            "@P1 bra.uni WD_%=;\n\t"                                          \
            "bra.uni WL_%=;\n\t"                                              \
            "WD_%=:\n\t}" :: "r"(_m), "r"(_p) : "memory");                    \
    }                                                                         \
} while (0)
#define BULK_G2S(dst, src, bytes, mbar) \
    asm volatile("cp.async.bulk.shared::cta.global.mbarrier::complete_tx::bytes " \
                 "[%0], [%1], %2, [%3];" \
                 :: "r"(dst), "l"(src), "r"(bytes), "r"(mbar) : "memory")
#define FENCE_ASYNC() asm volatile("fence.proxy.async.shared::cta;" ::: "memory")

// ---------------------------------------------------------------------------
// Fused QKV projection (tf32 mma). Weight rows stacked: [Wv(0..255); Wq(256..287);
// Wk(288..319)]. Block: 320 out-rows x 64 n. K=256 in 4 chunks of 64.
// x is transposed into smem so both operands are k(p)-fast.
// Also zeroes g_l for its n-slice.
// ---------------------------------------------------------------------------
#define PQ_SMEM ((64 * 68 + 320 * 68 + 320) * 4)

__global__ __launch_bounds__(256) void proj_qkv_kernel(
    const float* __restrict__ x,
    const float* __restrict__ Wq, const float* __restrict__ bq,
    const float* __restrict__ Wk, const float* __restrict__ bk,
    const float* __restrict__ Wv, const float* __restrict__ bv)
{
    extern __shared__ float sm[];
    float* xT     = sm;                 // [64 n][68]  (p fast)
    float* Ws     = sm + 64 * 68;       // [320 r][68] (p fast)
    float* bias_s = sm + 64 * 68 + 320 * 68;

    const int b   = blockIdx.y;
    const int n0  = blockIdx.x * 64;
    const int tid = threadIdx.x;
    const int w   = tid >> 5;
    const int ln  = tid & 31;
    const int g   = ln >> 2;
    const int t   = ln & 3;
    const int nmt = (w < 4) ? 3 : 2;    // m-tiles per warp: {w, w+8, w+16}

    if (tid < 64) g_l[(b << 12) + n0 + tid] = 0.f;
    if (tid < 256) bias_s[tid] = bv[tid];
    if (tid < 64)  bias_s[256 + tid] = (tid < 32) ? bq[tid] : bk[tid - 32];

    float4 acc[3][8];
#pragma unroll
    for (int mi = 0; mi < 3; mi++)
#pragma unroll
        for (int ct = 0; ct < 8; ct++) acc[mi][ct] = make_float4(0.f, 0.f, 0.f, 0.f);

    const int xn = tid & 63;            // n row for xT staging
    const int xq0 = tid >> 6;           // p-quad base (0..3)

    for (int p0 = 0; p0 < 256; p0 += 64) {
        // ---- stage xT[n][p] (transpose via register gather + STS.128) ----
#pragma unroll
        for (int i = 0; i < 4; i++) {
            const int p = (xq0 + 4 * i) << 2;
            const float* xp = x + (((size_t)((b << 8) + p0 + p)) << 12) + n0 + xn;
            float4 v;
            v.x = xp[0];
            v.y = xp[(size_t)1 << 12];
            v.z = xp[(size_t)2 << 12];
            v.w = xp[(size_t)3 << 12];
            *(float4*)&xT[xn * 68 + p] = v;
        }
        // ---- stage Ws[r][p] (straight copy) ----
#pragma unroll
        for (int it = 0; it < 20; it++) {
            const int idx = tid + (it << 8);
            const int r = idx >> 4, q = idx & 15;
            const float* rp = (r < 256) ? (Wv + r * 256)
                            : (r < 288) ? (Wq + (r - 256) * 256)
                                        : (Wk + (r - 288) * 256);
            *(float4*)&Ws[r * 68 + (q << 2)] = *(const float4*)&rp[p0 + (q << 2)];
        }
        __syncthreads();

#pragma unroll
        for (int kk = 0; kk < 8; kk++) {
            const int k = kk << 3;
            uint32_t bb[8][2], a[3][4];
#pragma unroll
            for (int ct = 0; ct < 8; ct++) {
                const int n = ct * 8 + g;
                bb[ct][0] = __float_as_uint(xT[n * 68 + k + t]);
                bb[ct][1] = __float_as_uint(xT[n * 68 + k + t + 4]);
            }
#pragma unroll
            for (int mi = 0; mi < 3; mi++) {
                if (mi < nmt) {
                    const int rb = (w + 8 * mi) * 16;
                    a[mi][0] = __float_as_uint(Ws[(rb + g) * 68 + k + t]);
                    a[mi][1] = __float_as_uint(Ws[(rb + g + 8) * 68 + k + t]);
                    a[mi][2] = __float_as_uint(Ws[(rb + g) * 68 + k + t + 4]);
                    a[mi][3] = __float_as_uint(Ws[(rb + g + 8) * 68 + k + t + 4]);
                }
            }
#pragma unroll
            for (int mi = 0; mi < 3; mi++)
                if (mi < nmt)
#pragma unroll
                    for (int ct = 0; ct < 8; ct++) mma8(acc[mi][ct], a[mi], bb[ct]);
        }
        __syncthreads();
    }

    // ---- epilogue: bias + tf32 round + route to g_V / g_Qn / g_Km ----
    auto store1 = [&](int row, int n, float v) {
        v = f2tf(v);
        if (row < 256) {
            g_V[(((size_t)(b * 64 + (n >> 6)) * 256) + row) * 64 +
                ((n & 63) ^ ((row & 7) << 2))] = v;
        } else if (row < 288) {
            g_Qn[(((size_t)b << 12) + n) * 32 + ((row - 256) ^ ((n & 7) << 2))] = v;
        } else {
            g_Km[(((size_t)b << 12) + n) * 32 + ((row - 288) ^ ((n & 7) << 2))] = v;
        }
    };
#pragma unroll
    for (int mi = 0; mi < 3; mi++) {
        if (mi < nmt) {
            const int r0 = (w + 8 * mi) * 16 + g;
            const int r1 = r0 + 8;
            const float b0 = bias_s[r0], b1 = bias_s[r1];
#pragma unroll
            for (int ct = 0; ct < 8; ct++) {
                const int n = n0 + ct * 8 + 2 * t;
                const float4 d = acc[mi][ct];
                store1(r0, n,     d.x + b0);
                store1(r0, n + 1, d.y + b0);
                store1(r1, n,     d.z + b1);
                store1(r1, n + 1, d.w + b1);
            }
        }
    }
}

// ---------------------------------------------------------------------------
// GEMM1: D[n][m] = Qn[n,:] . Km[m,:]  (128n x 128m, K=32, mma.sync tf32)
// Epilogue: g_P = tf32(exp(D)) in 64-chunk layout; rowsum fused via atomics.
// ---------------------------------------------------------------------------
__global__ __launch_bounds__(256) void gemm1_kernel()
{
    __shared__ float As[128 * 32];
    __shared__ float Bs[128 * 32];
    __shared__ __align__(8) unsigned long long s_mbar;
    const int n0 = blockIdx.x * 128;
    const int m0 = blockIdx.y * 128;
    const int b  = blockIdx.z;
    const int tid = threadIdx.x;
    const int wid = tid >> 5;
    const int ln  = tid & 31;
    const int g   = ln >> 2;
    const int t   = ln & 3;
    const int mw  = wid & 1;
    const int cw  = wid >> 1;

    const uint32_t mbar = smem_u32(&s_mbar);
    if (tid == 0) {
        MBAR_INIT(mbar, 1);
        FENCE_ASYNC();
        MBAR_EXPECT(mbar, 32768);
        BULK_G2S(smem_u32(As), g_Qn + (((size_t)b << 12) + n0) * 32, 16384, mbar);
        BULK_G2S(smem_u32(Bs), g_Km + (((size_t)b << 12) + m0) * 32, 16384, mbar);
    }
    __syncthreads();
    MBAR_WAIT(mbar, 0);

    const uint32_t* Au = (const uint32_t*)As;
    const uint32_t* Bu = (const uint32_t*)Bs;
    float4 acc[4][4];
#pragma unroll
    for (int mt = 0; mt < 4; mt++)
#pragma unroll
        for (int ct = 0; ct < 4; ct++) acc[mt][ct] = make_float4(0.f, 0.f, 0.f, 0.f);

    const uint32_t sx = (uint32_t)(g << 2);
#pragma unroll
    for (int kk = 0; kk < 4; kk++) {
        const int k = kk << 3;
        uint32_t a[4][4], bb[4][2];
#pragma unroll
        for (int mt = 0; mt < 4; mt++) {
            const int rb = mw * 64 + mt * 16;
            a[mt][0] = Au[(rb + g) * 32 + ((k + t) ^ sx)];
            a[mt][1] = Au[(rb + g + 8) * 32 + ((k + t) ^ sx)];
            a[mt][2] = Au[(rb + g) * 32 + ((k + t + 4) ^ sx)];
            a[mt][3] = Au[(rb + g + 8) * 32 + ((k + t + 4) ^ sx)];
        }
#pragma unroll
        for (int ct = 0; ct < 4; ct++) {
            const int cb = cw * 32 + ct * 8;
            bb[ct][0] = Bu[(cb + g) * 32 + ((k + t) ^ sx)];
            bb[ct][1] = Bu[(cb + g) * 32 + ((k + t + 4) ^ sx)];
        }
#pragma unroll
        for (int mt = 0; mt < 4; mt++)
#pragma unroll
            for (int ct = 0; ct < 4; ct++) mma8(acc[mt][ct], a[mt], bb[ct]);
    }

    float sum0[4], sum1[4];
#pragma unroll
    for (int ct = 0; ct < 4; ct++) { sum0[ct] = 0.f; sum1[ct] = 0.f; }

#pragma unroll
    for (int mt = 0; mt < 4; mt++) {
        const int n = n0 + mw * 64 + mt * 16 + g;
        const int nn = n & 63;
        const size_t tb = ((size_t)(b * 64 + (n >> 6)) << 12) * 64;
#pragma unroll
        for (int ct = 0; ct < 4; ct++) {
            const int m = m0 + cw * 32 + ct * 8 + 2 * t;
            const float4 d = acc[mt][ct];
            const float px = f2tf(__expf(d.x));
            const float py = f2tf(__expf(d.y));
            const float pz = f2tf(__expf(d.z));
            const float pw = f2tf(__expf(d.w));
            const uint32_t sm0 = (uint32_t)((m & 7) << 2);
            const uint32_t sm1 = (uint32_t)(((m + 1) & 7) << 2);
            g_P[tb + (size_t)m * 64 + (nn ^ sm0)]             = px;
            g_P[tb + (size_t)(m + 1) * 64 + (nn ^ sm1)]       = py;
            g_P[tb + (size_t)m * 64 + ((nn + 8) ^ sm0)]       = pz;
            g_P[tb + (size_t)(m + 1) * 64 + ((nn + 8) ^ sm1)] = pw;
            sum0[ct] += px + pz;
            sum1[ct] += py + pw;
        }
    }
#pragma unroll
    for (int ct = 0; ct < 4; ct++) {
#pragma unroll
        for (int d = 4; d < 32; d <<= 1) {
            sum0[ct] += __shfl_xor_sync(0xffffffffu, sum0[ct], d);
            sum1[ct] += __shfl_xor_sync(0xffffffffu, sum1[ct], d);
        }
    }
    if (g == 0) {
#pragma unroll
        for (int ct = 0; ct < 4; ct++) {
            const int m = m0 + cw * 32 + ct * 8 + 2 * t;
            atomicAdd(&g_l[(b << 12) + m],     sum0[ct]);
            atomicAdd(&g_l[(b << 12) + m + 1], sum1[ct]);
        }
    }
}

// ---------------------------------------------------------------------------
// GEMM2: D2[m][c] = sum_n P[m][n] V[c][n]  (128m x 256c, K=4096, 64-n chunks,
// 2-stage 96KB bulk pipeline). Epilogue: out = gamma*D2/l + x.
// ---------------------------------------------------------------------------
#define NSTG2 2
#define STGB  (32768 + 65536)            // P 32KB + V 64KB
#define G2_SMEM (NSTG2 * STGB)           // 192KB

__global__ __launch_bounds__(256, 1) void gemm2_kernel(
    const float* __restrict__ xin, const float* __restrict__ gamma,
    float* __restrict__ out)
{
    extern __shared__ __align__(1024) char sm2[];
    __shared__ __align__(8) unsigned long long s_mb[NSTG2];

    const int m0 = blockIdx.x * 128;
    const int b  = blockIdx.y;
    const int tid = threadIdx.x;
    const int wid = tid >> 5;
    const int ln  = tid & 31;
    const int g   = ln >> 2;
    const int t   = ln & 3;
    const int mw  = wid & 1;
    const int cw  = wid >> 1;

    uint32_t mb[NSTG2];
#pragma unroll
    for (int s = 0; s < NSTG2; s++) mb[s] = smem_u32(&s_mb[s]);
    const uint32_t smbase = smem_u32(sm2);

    const float* Pg = g_P + ((size_t)(b * 64) << 12) * 64 + ((size_t)m0 * 64);
    const float* Vg = g_V + ((size_t)(b * 64) * C_) * 64;

    if (tid == 0) {
#pragma unroll
        for (int s = 0; s < NSTG2; s++) MBAR_INIT(mb[s], 1);
        FENCE_ASYNC();
#pragma unroll
        for (int s = 0; s < NSTG2; s++) {
            MBAR_EXPECT(mb[s], STGB);
            BULK_G2S(smbase + s * STGB,
                     Pg + ((size_t)s << 12) * 64, 32768, mb[s]);
            BULK_G2S(smbase + s * STGB + 32768,
                     Vg + (size_t)s * C_ * 64, 65536, mb[s]);
        }
    }
    __syncthreads();

    float4 acc[4][8];
#pragma unroll
    for (int mt = 0; mt < 4; mt++)
#pragma unroll
        for (int ct = 0; ct < 8; ct++) acc[mt][ct] = make_float4(0.f, 0.f, 0.f, 0.f);

    const uint32_t sx = (uint32_t)(g << 2);
    int ph[NSTG2] = {0, 0};

    for (int ch = 0; ch < 64; ch++) {
        const int st = ch & 1;
        MBAR_WAIT(mb[st], ph[st]);
        ph[st] ^= 1;

        const uint32_t* Pu = (const uint32_t*)(sm2 + st * STGB);
        const uint32_t* Vu = (const uint32_t*)(sm2 + st * STGB + 32768);
#pragma unroll
        for (int kk = 0; kk < 8; kk++) {
            const int k = kk << 3;
            uint32_t a[4][4], bb[8][2];
#pragma unroll
            for (int mt = 0; mt < 4; mt++) {
                const int rb = mw * 64 + mt * 16;
                a[mt][0] = Pu[(rb + g) * 64 + ((k + t) ^ sx)];
                a[mt][1] = Pu[(rb + g + 8) * 64 + ((k + t) ^ sx)];
                a[mt][2] = Pu[(rb + g) * 64 + ((k + t + 4) ^ sx)];
                a[mt][3] = Pu[(rb + g + 8) * 64 + ((k + t + 4) ^ sx)];
            }
#pragma unroll
            for (int ct = 0; ct < 8; ct++) {
                const int cb = cw * 64 + ct * 8;
                bb[ct][0] = Vu[(cb + g) * 64 + ((k + t) ^ sx)];
                bb[ct][1] = Vu[(cb + g) * 64 + ((k + t + 4) ^ sx)];
            }
#pragma unroll
            for (int mt = 0; mt < 4; mt++)
#pragma unroll
                for (int ct = 0; ct < 8; ct++) mma8(acc[mt][ct], a[mt], bb[ct]);
        }
        __syncthreads();
        if (tid == 0 && ch + NSTG2 < 64) {
            const int nc = ch + NSTG2;
            MBAR_EXPECT(mb[st], STGB);
            BULK_G2S(smbase + st * STGB,
                     Pg + ((size_t)nc << 12) * 64, 32768, mb[st]);
            BULK_G2S(smbase + st * STGB + 32768,
                     Vg + (size_t)nc * C_ * 64, 65536, mb[st]);
        }
    }

    const float gam = *gamma;
    float il0[4], il1[4];
#pragma unroll
    for (int mt = 0; mt < 4; mt++) {
        const int mm = m0 + mw * 64 + mt * 16 + g;
        il0[mt] = 1.0f / g_l[(b << 12) + mm];
        il1[mt] = 1.0f / g_l[(b << 12) + mm + 8];
    }
#pragma unroll
    for (int mt = 0; mt < 4; mt++) {
        const int m = m0 + mw * 64 + mt * 16 + g;
#pragma unroll
        for (int ct = 0; ct < 8; ct++) {
            const int c = cw * 64 + ct * 8 + 2 * t;
            const float4 d = acc[mt][ct];
            const size_t i00 = (((size_t)(b << 8) + c) << 12) + m;
            const size_t i01 = i00 + N_;
            out[i00]     = gam * d.x * il0[mt] + xin[i00];
            out[i01]     = gam * d.y * il0[mt] + xin[i01];
            out[i00 + 8] = gam * d.z * il1[mt] + xin[i00 + 8];
            out[i01 + 8] = gam * d.w * il1[mt] + xin[i01 + 8];
        }
    }
}

// ---------------------------------------------------------------------------
extern "C" void kernel_launch(void* const* d_in, const int* in_sizes, int n_in,
                              void* d_out, int out_size)
{
    const float* x     = (const float*)d_in[0];
    const float* Wq    = (const float*)d_in[1];
    const float* bq    = (const float*)d_in[2];
    const float* Wk    = (const float*)d_in[3];
    const float* bk    = (const float*)d_in[4];
    const float* Wv    = (const float*)d_in[5];
    const float* bv    = (const float*)d_in[6];
    const float* gamma = (const float*)d_in[7];
    float* out = (float*)d_out;

    static bool attr_set = false;
    if (!attr_set) {
        cudaFuncSetAttribute(proj_qkv_kernel,
            cudaFuncAttributeMaxDynamicSharedMemorySize, PQ_SMEM);
        cudaFuncSetAttribute(gemm2_kernel,
            cudaFuncAttributeMaxDynamicSharedMemorySize, G2_SMEM);
        attr_set = true;
    }

    proj_qkv_kernel<<<dim3(N_ / 64, B_), 256, PQ_SMEM>>>(
        x, Wq, bq, Wk, bk, Wv, bv);                       // g_Qn, g_Km, g_V, g_l=0
    gemm1_kernel<<<dim3(N_ / 128, N_ / 128, B_), 256>>>();  // g_P + g_l
    gemm2_kernel<<<dim3(N_ / 128, B_), 256, G2_SMEM>>>(x, gamma, out);
}